// round 10
// baseline (speedup 1.0000x reference)
#include <cuda_runtime.h>
#include <cstdint>

#define MAXQ 4096
#define TPB 256
#define TPB1K 1024

// Packed per-query params
static __device__ float4 g_px[MAXQ];   // (c0, c1, c2, Ix as float bits) for x-stage
static __device__ int    g_Iy[MAXQ];
static __device__ float4 g_dy[MAXQ];   // (h0, h1, h2, h3*r) for y-stage

// Precompute: axis staged in smem so the binary search hits smem.
__global__ void precompute_kernel(const float* __restrict__ xaxis,
                                  const float* __restrict__ yaxis,
                                  const float* __restrict__ xs,
                                  const float* __restrict__ ys,
                                  int N) {
    extern __shared__ float ax[];
    bool is_y = (blockIdx.y != 0);
    const float* axis = is_y ? yaxis : xaxis;
    const float* qs   = is_y ? ys    : xs;
    for (int i = threadIdx.x; i < N; i += blockDim.x)
        ax[i] = axis[i];
    __syncthreads();

    int q = blockIdx.x * blockDim.x + threadIdx.x;
    if (q >= N) return;
    float v = qs[q];
    // Exact replica of jnp.searchsorted(axis[1:-1], v, side='left')
    int lo = 0, hi = N - 2;
    while (lo < hi) {
        int mid = (lo + hi) >> 1;
        if (ax[1 + mid] < v) lo = mid + 1; else hi = mid;
    }
    int I = lo;
    float x0 = ax[I], x1 = ax[I + 1], x2 = ax[I + 2];
    float dx = x1 - x0;
    float t = (v - x0) / dx;
    float t2 = t * t, t3 = t2 * t;
    float h0 = 1.0f - 3.0f * t2 + 2.0f * t3;
    float h1 = t - 2.0f * t2 + t3;
    float h2 = 3.0f * t2 - 2.0f * t3;
    float h3 = t3 - t2;
    float r = dx / (x2 - x1);
    if (!is_y) {
        g_px[q] = make_float4(h0 - h1, h1 + h2 - h3 * r, h3 * r, __int_as_float(I));
    } else {
        g_Iy[q] = I;
        g_dy[q] = make_float4(h0, h1, h2, h3 * r);
    }
}

// 4-batch fused kernel, 1024 threads, single pass (N==1024).
// Fill loads ALL global data (a, b, s2 per batch), folds the column term
// e = d.y*(b-a) + d.w*(s2-b) into 4 registers, and builds w4 in smem.
// Compute loop is then pure: params LDG.128 + 3 random LDS.128 + 4 STG.
__global__ __launch_bounds__(TPB1K, 2) void fused4_1k_kernel(const float* __restrict__ signal,
                                                             float* __restrict__ out,
                                                             int N) {
    extern __shared__ float4 w4[];     // N entries (16KB), 16B-aligned -> LDS.128
    int bq = blockIdx.x / N;
    int qy = blockIdx.x - bq * N;
    int Iy = g_Iy[qy];
    float4 d = g_dy[qy];
    size_t pstride = (size_t)N * N;
    const float* __restrict__ rbase = signal + (size_t)(bq * 4) * pstride + (size_t)Iy * N;
    float* __restrict__ obase = out + (size_t)(bq * 4) * pstride + (size_t)qy * N;

    int q = threadIdx.x;
    float e[4];
    {
        float wv[4];
#pragma unroll
        for (int k = 0; k < 4; ++k) {
            const float* __restrict__ rk = rbase + (size_t)k * pstride;
            float a  = __ldg(rk + q);
            float b  = __ldg(rk + N + q);
            float s2 = __ldg(rk + 2 * N + q);
            e[k]  = d.y * (b - a) + d.w * (s2 - b);
            wv[k] = d.x * a + d.z * b;
        }
        w4[q] = make_float4(wv[0], wv[1], wv[2], wv[3]);
    }
    __syncthreads();

    {
        float4 p = g_px[q];
        int I = __float_as_int(p.w);
        float4 wa = w4[I];
        float4 wb = w4[I + 1];
        float4 wc = w4[I + 2];
        obase[0 * pstride + q] = p.x * wa.x + p.y * wb.x + p.z * wc.x + e[0];
        obase[1 * pstride + q] = p.x * wa.y + p.y * wb.y + p.z * wc.y + e[1];
        obase[2 * pstride + q] = p.x * wa.z + p.y * wb.z + p.z * wc.z + e[2];
        obase[3 * pstride + q] = p.x * wa.w + p.y * wb.w + p.z * wc.w + e[3];
    }
}

// 4-batch fused kernel (proven 72.8us at R9) — fallback for other N.
template <int ITERS>
__global__ __launch_bounds__(512, 4) void fused4_kernel(const float* __restrict__ signal,
                                                        float* __restrict__ out,
                                                        int N) {
    extern __shared__ float4 w4[];
    int bq = blockIdx.x / N;
    int qy = blockIdx.x - bq * N;
    int Iy = g_Iy[qy];
    float4 d = g_dy[qy];
    size_t pstride = (size_t)N * N;
    const float* __restrict__ rbase = signal + (size_t)(bq * 4) * pstride + (size_t)Iy * N;
    float* __restrict__ obase = out + (size_t)(bq * 4) * pstride + (size_t)qy * N;

    float colt[ITERS][4];
#pragma unroll
    for (int it = 0; it < ITERS; ++it) {
        int q = threadIdx.x + it * 512;
        float wv[4];
#pragma unroll
        for (int k = 0; k < 4; ++k) {
            float a = __ldg(rbase + (size_t)k * pstride + q);
            float b = __ldg(rbase + (size_t)k * pstride + N + q);
            colt[it][k] = d.y * (b - a) - d.w * b;
            wv[k] = d.x * a + d.z * b;
        }
        w4[q] = make_float4(wv[0], wv[1], wv[2], wv[3]);
    }
    __syncthreads();
#pragma unroll
    for (int it = 0; it < ITERS; ++it) {
        int q = threadIdx.x + it * 512;
        float4 p = g_px[q];
        int I = __float_as_int(p.w);
        float4 wa = w4[I];
        float4 wb = w4[I + 1];
        float4 wc = w4[I + 2];
#pragma unroll
        for (int k = 0; k < 4; ++k) {
            float ga = (k == 0) ? wa.x : (k == 1) ? wa.y : (k == 2) ? wa.z : wa.w;
            float gb = (k == 0) ? wb.x : (k == 1) ? wb.y : (k == 2) ? wb.z : wb.w;
            float gc = (k == 0) ? wc.x : (k == 1) ? wc.y : (k == 2) ? wc.z : wc.w;
            float g = p.x * ga + p.y * gb + p.z * gc;
            float s2 = __ldg(rbase + (size_t)k * pstride + 2 * N + q);
            obase[(size_t)k * pstride + q] = g + colt[it][k] + d.w * s2;
        }
    }
}

// Generic single-batch fallback
__global__ __launch_bounds__(TPB) void fused_kernel_gen(const float* __restrict__ signal,
                                                        float* __restrict__ out,
                                                        int N) {
    extern __shared__ float w[];
    int b  = blockIdx.x / N;
    int qy = blockIdx.x - b * N;
    int Iy = g_Iy[qy];
    float4 d = g_dy[qy];
    size_t plane = (size_t)b * N * N;
    const float* __restrict__ r0 = signal + plane + (size_t)Iy * N;
    const float* __restrict__ r1 = r0 + N;
    const float* __restrict__ r2 = r1 + N;
    float* __restrict__ orow = out + plane + (size_t)qy * N;

    for (int q = threadIdx.x; q < N; q += TPB)
        w[q] = d.x * __ldg(r0 + q) + d.z * __ldg(r1 + q);
    __syncthreads();
    for (int q = threadIdx.x; q < N; q += TPB) {
        float4 p = g_px[q];
        int I = __float_as_int(p.w);
        float g = p.x * w[I] + p.y * w[I + 1] + p.z * w[I + 2];
        float a = __ldg(r0 + q), bb = __ldg(r1 + q), s2 = __ldg(r2 + q);
        orow[q] = g + d.y * (bb - a) + d.w * (s2 - bb);
    }
}

extern "C" void kernel_launch(void* const* d_in, const int* in_sizes, int n_in,
                              void* d_out, int out_size) {
    const float* xaxis  = (const float*)d_in[0];
    const float* yaxis  = (const float*)d_in[1];
    const float* signal = (const float*)d_in[2];
    const float* xs     = (const float*)d_in[3];
    const float* ys     = (const float*)d_in[4];
    float* out = (float*)d_out;

    int N = in_sizes[0];                       // 1024
    int B = (int)((long long)in_sizes[2] / ((long long)N * N));  // 32

    dim3 pg((N + TPB - 1) / TPB, 2);
    precompute_kernel<<<pg, TPB, N * sizeof(float)>>>(xaxis, yaxis, xs, ys, N);

    if ((B % 4) == 0 && N == 1024) {
        fused4_1k_kernel<<<(B / 4) * N, TPB1K, N * sizeof(float4)>>>(signal, out, N);
    } else if ((B % 4) == 0 && N == 2048) {
        fused4_kernel<4><<<(B / 4) * N, 512, N * sizeof(float4)>>>(signal, out, N);
    } else if ((B % 4) == 0 && N == 512) {
        fused4_kernel<1><<<(B / 4) * N, 512, N * sizeof(float4)>>>(signal, out, N);
    } else {
        fused_kernel_gen<<<B * N, TPB, N * sizeof(float)>>>(signal, out, N);
    }
}

// round 13
// speedup vs baseline: 1.2675x; 1.2675x over previous
#include <cuda_runtime.h>
#include <cuda_fp16.h>
#include <cstdint>

#define MAXQ 4096
#define TPB 256

// Packed per-query params
static __device__ float4 g_px[MAXQ];   // (c0, c1, c2, Ix as float bits) for x-stage
static __device__ int    g_Iy[MAXQ];
static __device__ float4 g_dy[MAXQ];   // (h0, h1, h2, h3*r) for y-stage

// Precompute: axis staged in smem so the binary search hits smem.
__global__ void precompute_kernel(const float* __restrict__ xaxis,
                                  const float* __restrict__ yaxis,
                                  const float* __restrict__ xs,
                                  const float* __restrict__ ys,
                                  int N) {
    extern __shared__ float ax[];
    bool is_y = (blockIdx.y != 0);
    const float* axis = is_y ? yaxis : xaxis;
    const float* qs   = is_y ? ys    : xs;
    for (int i = threadIdx.x; i < N; i += blockDim.x)
        ax[i] = axis[i];
    __syncthreads();

    int q = blockIdx.x * blockDim.x + threadIdx.x;
    if (q >= N) return;
    float v = qs[q];
    // Exact replica of jnp.searchsorted(axis[1:-1], v, side='left')
    int lo = 0, hi = N - 2;
    while (lo < hi) {
        int mid = (lo + hi) >> 1;
        if (ax[1 + mid] < v) lo = mid + 1; else hi = mid;
    }
    int I = lo;
    float x0 = ax[I], x1 = ax[I + 1], x2 = ax[I + 2];
    float dx = x1 - x0;
    float t = (v - x0) / dx;
    float t2 = t * t, t3 = t2 * t;
    float h0 = 1.0f - 3.0f * t2 + 2.0f * t3;
    float h1 = t - 2.0f * t2 + t3;
    float h2 = 3.0f * t2 - 2.0f * t3;
    float h3 = t3 - t2;
    float r = dx / (x2 - x1);
    if (!is_y) {
        g_px[q] = make_float4(h0 - h1, h1 + h2 - h3 * r, h3 * r, __int_as_float(I));
    } else {
        g_Iy[q] = I;
        g_dy[q] = make_float4(h0, h1, h2, h3 * r);
    }
}

// 4-batch fused kernel, R9 skeleton (512 thr, ITERS=2) with the gathered
// array stored as half4 (uint2): each random tap is an LDS.64 (~5 conflict
// phases) instead of LDS.128 (~10). Column term stays fp32-exact.
template <int ITERS>
__global__ __launch_bounds__(512, 4) void fused4h_kernel(const float* __restrict__ signal,
                                                         float* __restrict__ out,
                                                         int N) {
    extern __shared__ uint2 w8[];      // N entries: (half2(w0,w1), half2(w2,w3))
    int bq = blockIdx.x / N;
    int qy = blockIdx.x - bq * N;
    int Iy = g_Iy[qy];
    float4 d = g_dy[qy];
    size_t pstride = (size_t)N * N;
    const float* __restrict__ rbase = signal + (size_t)(bq * 4) * pstride + (size_t)Iy * N;
    float* __restrict__ obase = out + (size_t)(bq * 4) * pstride + (size_t)qy * N;

    float colt[ITERS][4];

#pragma unroll
    for (int it = 0; it < ITERS; ++it) {
        int q = threadIdx.x + it * 512;
        float wv[4];
#pragma unroll
        for (int k = 0; k < 4; ++k) {
            float a = __ldg(rbase + (size_t)k * pstride + q);
            float b = __ldg(rbase + (size_t)k * pstride + N + q);
            colt[it][k] = d.y * (b - a) - d.w * b;
            wv[k] = d.x * a + d.z * b;
        }
        __half2 h01 = __floats2half2_rn(wv[0], wv[1]);
        __half2 h23 = __floats2half2_rn(wv[2], wv[3]);
        w8[q] = make_uint2(*reinterpret_cast<uint32_t*>(&h01),
                           *reinterpret_cast<uint32_t*>(&h23));
    }
    __syncthreads();

#pragma unroll
    for (int it = 0; it < ITERS; ++it) {
        int q = threadIdx.x + it * 512;
        float4 p = g_px[q];
        int I = __float_as_int(p.w);
        uint2 ua = w8[I];
        uint2 ub = w8[I + 1];
        uint2 uc = w8[I + 2];
        float2 a01 = __half22float2(*reinterpret_cast<__half2*>(&ua.x));
        float2 a23 = __half22float2(*reinterpret_cast<__half2*>(&ua.y));
        float2 b01 = __half22float2(*reinterpret_cast<__half2*>(&ub.x));
        float2 b23 = __half22float2(*reinterpret_cast<__half2*>(&ub.y));
        float2 c01 = __half22float2(*reinterpret_cast<__half2*>(&uc.x));
        float2 c23 = __half22float2(*reinterpret_cast<__half2*>(&uc.y));
        float g0 = p.x * a01.x + p.y * b01.x + p.z * c01.x;
        float g1 = p.x * a01.y + p.y * b01.y + p.z * c01.y;
        float g2 = p.x * a23.x + p.y * b23.x + p.z * c23.x;
        float g3 = p.x * a23.y + p.y * b23.y + p.z * c23.y;
        float s20 = __ldg(rbase + 0 * pstride + 2 * N + q);
        float s21 = __ldg(rbase + 1 * pstride + 2 * N + q);
        float s22 = __ldg(rbase + 2 * pstride + 2 * N + q);
        float s23 = __ldg(rbase + 3 * pstride + 2 * N + q);
        obase[0 * pstride + q] = g0 + colt[it][0] + d.w * s20;
        obase[1 * pstride + q] = g1 + colt[it][1] + d.w * s21;
        obase[2 * pstride + q] = g2 + colt[it][2] + d.w * s22;
        obase[3 * pstride + q] = g3 + colt[it][3] + d.w * s23;
    }
}

// 4-batch fp32 kernel (proven 72.8us at R9) — fallback.
template <int ITERS>
__global__ __launch_bounds__(512, 4) void fused4_kernel(const float* __restrict__ signal,
                                                        float* __restrict__ out,
                                                        int N) {
    extern __shared__ float4 w4[];
    int bq = blockIdx.x / N;
    int qy = blockIdx.x - bq * N;
    int Iy = g_Iy[qy];
    float4 d = g_dy[qy];
    size_t pstride = (size_t)N * N;
    const float* __restrict__ rbase = signal + (size_t)(bq * 4) * pstride + (size_t)Iy * N;
    float* __restrict__ obase = out + (size_t)(bq * 4) * pstride + (size_t)qy * N;

    float colt[ITERS][4];
#pragma unroll
    for (int it = 0; it < ITERS; ++it) {
        int q = threadIdx.x + it * 512;
        float wv[4];
#pragma unroll
        for (int k = 0; k < 4; ++k) {
            float a = __ldg(rbase + (size_t)k * pstride + q);
            float b = __ldg(rbase + (size_t)k * pstride + N + q);
            colt[it][k] = d.y * (b - a) - d.w * b;
            wv[k] = d.x * a + d.z * b;
        }
        w4[q] = make_float4(wv[0], wv[1], wv[2], wv[3]);
    }
    __syncthreads();
#pragma unroll
    for (int it = 0; it < ITERS; ++it) {
        int q = threadIdx.x + it * 512;
        float4 p = g_px[q];
        int I = __float_as_int(p.w);
        float4 wa = w4[I];
        float4 wb = w4[I + 1];
        float4 wc = w4[I + 2];
#pragma unroll
        for (int k = 0; k < 4; ++k) {
            float ga = (k == 0) ? wa.x : (k == 1) ? wa.y : (k == 2) ? wa.z : wa.w;
            float gb = (k == 0) ? wb.x : (k == 1) ? wb.y : (k == 2) ? wb.z : wb.w;
            float gc = (k == 0) ? wc.x : (k == 1) ? wc.y : (k == 2) ? wc.z : wc.w;
            float g = p.x * ga + p.y * gb + p.z * gc;
            float s2 = __ldg(rbase + (size_t)k * pstride + 2 * N + q);
            obase[(size_t)k * pstride + q] = g + colt[it][k] + d.w * s2;
        }
    }
}

// Generic single-batch fallback
__global__ __launch_bounds__(TPB) void fused_kernel_gen(const float* __restrict__ signal,
                                                        float* __restrict__ out,
                                                        int N) {
    extern __shared__ float w[];
    int b  = blockIdx.x / N;
    int qy = blockIdx.x - b * N;
    int Iy = g_Iy[qy];
    float4 d = g_dy[qy];
    size_t plane = (size_t)b * N * N;
    const float* __restrict__ r0 = signal + plane + (size_t)Iy * N;
    const float* __restrict__ r1 = r0 + N;
    const float* __restrict__ r2 = r1 + N;
    float* __restrict__ orow = out + plane + (size_t)qy * N;

    for (int q = threadIdx.x; q < N; q += TPB)
        w[q] = d.x * __ldg(r0 + q) + d.z * __ldg(r1 + q);
    __syncthreads();
    for (int q = threadIdx.x; q < N; q += TPB) {
        float4 p = g_px[q];
        int I = __float_as_int(p.w);
        float g = p.x * w[I] + p.y * w[I + 1] + p.z * w[I + 2];
        float a = __ldg(r0 + q), bb = __ldg(r1 + q), s2 = __ldg(r2 + q);
        orow[q] = g + d.y * (bb - a) + d.w * (s2 - bb);
    }
}

extern "C" void kernel_launch(void* const* d_in, const int* in_sizes, int n_in,
                              void* d_out, int out_size) {
    const float* xaxis  = (const float*)d_in[0];
    const float* yaxis  = (const float*)d_in[1];
    const float* signal = (const float*)d_in[2];
    const float* xs     = (const float*)d_in[3];
    const float* ys     = (const float*)d_in[4];
    float* out = (float*)d_out;

    int N = in_sizes[0];                       // 1024
    int B = (int)((long long)in_sizes[2] / ((long long)N * N));  // 32

    dim3 pg((N + TPB - 1) / TPB, 2);
    precompute_kernel<<<pg, TPB, N * sizeof(float)>>>(xaxis, yaxis, xs, ys, N);

    if ((B % 4) == 0 && N == 1024) {
        fused4h_kernel<2><<<(B / 4) * N, 512, N * sizeof(uint2)>>>(signal, out, N);
    } else if ((B % 4) == 0 && N == 2048) {
        fused4_kernel<4><<<(B / 4) * N, 512, N * sizeof(float4)>>>(signal, out, N);
    } else if ((B % 4) == 0 && N == 512) {
        fused4_kernel<1><<<(B / 4) * N, 512, N * sizeof(float4)>>>(signal, out, N);
    } else {
        fused_kernel_gen<<<B * N, TPB, N * sizeof(float)>>>(signal, out, N);
    }
}